// round 5
// baseline (speedup 1.0000x reference)
#include <cuda_runtime.h>
#include <stdint.h>

#define N_NODES 100000
#define GAMMA 0.5f
#define FIX_SCALE 8388608.0f        // 2^23
#define INV_FIX_SCALE (1.0f / 8388608.0f)
#define SMEM_NODES 57344            // 224KB of the avg table lives in smem
#define OUT_GRID 152                // one persistent block per SM
#define OUT_BLOCK 1024

// packed per-node accumulator: high 32 = count, low 32 = fixed-point sum (2^23 scale)
__device__ unsigned long long g_pack[N_NODES];
__device__ float g_avg[N_NODES];

__global__ void zero_kernel() {
    int i = blockIdx.x * blockDim.x + threadIdx.x;
    if (i < N_NODES) g_pack[i] = 0ull;
}

__device__ __forceinline__ unsigned long long pack_edge(float m) {
    unsigned fix = __float2uint_rn(m * FIX_SCALE);
    return (1ull << 32) | (unsigned long long)fix;
}

// Scatter: one 64-bit REDG per edge carrying both count(+1) and fixed-point mask sum.
// Measured at the REDG spread-address floor (~31us) — leave as-is.
__global__ void scatter_kernel(const float* __restrict__ mask,
                               const int* __restrict__ src,
                               int E) {
    int i4 = (blockIdx.x * blockDim.x + threadIdx.x) * 4;
    if (i4 + 3 < E) {
        float4 m = __ldcg(reinterpret_cast<const float4*>(mask + i4));
        int4 s = __ldcg(reinterpret_cast<const int4*>(src + i4));
        if ((unsigned)s.x < N_NODES) atomicAdd(&g_pack[s.x], pack_edge(m.x));
        if ((unsigned)s.y < N_NODES) atomicAdd(&g_pack[s.y], pack_edge(m.y));
        if ((unsigned)s.z < N_NODES) atomicAdd(&g_pack[s.z], pack_edge(m.z));
        if ((unsigned)s.w < N_NODES) atomicAdd(&g_pack[s.w], pack_edge(m.w));
    } else {
        for (int i = i4; i < E; i++) {
            int s = src[i];
            if ((unsigned)s < N_NODES) atomicAdd(&g_pack[s], pack_edge(mask[i]));
        }
    }
}

__global__ void avg_kernel() {
    int i = blockIdx.x * blockDim.x + threadIdx.x;
    if (i < N_NODES) {
        unsigned long long p = g_pack[i];
        float cnt = (float)(unsigned)(p >> 32);
        float sum = (float)(unsigned)(p & 0xffffffffull) * INV_FIX_SCALE;
        g_avg[i] = sum / fmaxf(cnt, 1.0f);
    }
}

// Branch-free table lookup: predicated LDS / LDG pair (no BSSY, MLP preserved).
// Index clamped to [0, N_NODES) for safety (data is in-range by construction).
__device__ __forceinline__ float lookup(uint32_t s_base, unsigned idx) {
    idx = min(idx, (unsigned)(N_NODES - 1));
    uint32_t saddr = s_base + idx * 4u;
    const float* gaddr = &g_avg[idx];
    float v;
    asm volatile(
        "{\n\t"
        ".reg .pred p;\n\t"
        "setp.lt.u32 p, %1, %2;\n\t"
        "@p  ld.shared.f32 %0, [%3];\n\t"
        "@!p ld.global.ca.f32 %0, [%4];\n\t"
        "}"
        : "=f"(v)
        : "r"(idx), "n"(SMEM_NODES), "r"(saddr), "l"(gaddr));
    return v;
}

// out[e] = 0.5*mask[e] + 0.25*(avg[src[e]] + avg[dst[e]])
// Persistent blocks; 224KB avg table in smem; 8 edges (16 predicated lookups)
// per thread-iteration so all gathers issue back-to-back.
__global__ void __launch_bounds__(OUT_BLOCK, 1)
out_kernel(const float* __restrict__ mask,
           const int* __restrict__ src,
           const int* __restrict__ dst,
           float* __restrict__ out,
           int E) {
    extern __shared__ float s_avg[];
    uint32_t s_base = (uint32_t)__cvta_generic_to_shared(s_avg);
    for (int i = threadIdx.x; i < SMEM_NODES; i += OUT_BLOCK)
        s_avg[i] = g_avg[i];
    __syncthreads();

    int nG = E >> 3;  // groups of 8 edges
    int stride = gridDim.x * OUT_BLOCK;
    for (int g = blockIdx.x * OUT_BLOCK + threadIdx.x; g < nG; g += stride) {
        int i8 = g * 8;
        float4 m0 = __ldcg(reinterpret_cast<const float4*>(mask + i8));
        float4 m1 = __ldcg(reinterpret_cast<const float4*>(mask + i8 + 4));
        int4 s0 = __ldcg(reinterpret_cast<const int4*>(src + i8));
        int4 s1 = __ldcg(reinterpret_cast<const int4*>(src + i8 + 4));
        int4 d0 = __ldcg(reinterpret_cast<const int4*>(dst + i8));
        int4 d1 = __ldcg(reinterpret_cast<const int4*>(dst + i8 + 4));

        float vs0 = lookup(s_base, (unsigned)s0.x);
        float vs1 = lookup(s_base, (unsigned)s0.y);
        float vs2 = lookup(s_base, (unsigned)s0.z);
        float vs3 = lookup(s_base, (unsigned)s0.w);
        float vs4 = lookup(s_base, (unsigned)s1.x);
        float vs5 = lookup(s_base, (unsigned)s1.y);
        float vs6 = lookup(s_base, (unsigned)s1.z);
        float vs7 = lookup(s_base, (unsigned)s1.w);
        float vd0 = lookup(s_base, (unsigned)d0.x);
        float vd1 = lookup(s_base, (unsigned)d0.y);
        float vd2 = lookup(s_base, (unsigned)d0.z);
        float vd3 = lookup(s_base, (unsigned)d0.w);
        float vd4 = lookup(s_base, (unsigned)d1.x);
        float vd5 = lookup(s_base, (unsigned)d1.y);
        float vd6 = lookup(s_base, (unsigned)d1.z);
        float vd7 = lookup(s_base, (unsigned)d1.w);

        float4 o0, o1;
        o0.x = (1.0f - GAMMA) * m0.x + (GAMMA * 0.5f) * (vs0 + vd0);
        o0.y = (1.0f - GAMMA) * m0.y + (GAMMA * 0.5f) * (vs1 + vd1);
        o0.z = (1.0f - GAMMA) * m0.z + (GAMMA * 0.5f) * (vs2 + vd2);
        o0.w = (1.0f - GAMMA) * m0.w + (GAMMA * 0.5f) * (vs3 + vd3);
        o1.x = (1.0f - GAMMA) * m1.x + (GAMMA * 0.5f) * (vs4 + vd4);
        o1.y = (1.0f - GAMMA) * m1.y + (GAMMA * 0.5f) * (vs5 + vd5);
        o1.z = (1.0f - GAMMA) * m1.z + (GAMMA * 0.5f) * (vs6 + vd6);
        o1.w = (1.0f - GAMMA) * m1.w + (GAMMA * 0.5f) * (vs7 + vd7);
        __stcg(reinterpret_cast<float4*>(out + i8), o0);
        __stcg(reinterpret_cast<float4*>(out + i8 + 4), o1);
    }

    // tail (E % 8 leftovers)
    int tail = E & 7;
    if (blockIdx.x == 0 && (int)threadIdx.x < tail) {
        int i = (E & ~7) + threadIdx.x;
        float a = lookup(s_base, (unsigned)src[i]) + lookup(s_base, (unsigned)dst[i]);
        out[i] = (1.0f - GAMMA) * mask[i] + (GAMMA * 0.5f) * a;
    }
}

extern "C" void kernel_launch(void* const* d_in, const int* in_sizes, int n_in,
                              void* d_out, int out_size) {
    const float* mask = (const float*)d_in[0];
    const int* edge_index = (const int*)d_in[1];  // int32 (JAX x64 disabled)
    float* out = (float*)d_out;

    int E = in_sizes[0];
    const int* src = edge_index;       // row 0
    const int* dst = edge_index + E;   // row 1

    cudaFuncSetAttribute(out_kernel, cudaFuncAttributeMaxDynamicSharedMemorySize,
                         SMEM_NODES * (int)sizeof(float));

    {
        int threads = 256;
        int blocks = (N_NODES + threads - 1) / threads;
        zero_kernel<<<blocks, threads>>>();
    }
    {
        int threads = 256;
        int work = (E + 3) / 4;
        int blocks = (work + threads - 1) / threads;
        scatter_kernel<<<blocks, threads>>>(mask, src, E);
    }
    {
        int threads = 256;
        int blocks = (N_NODES + threads - 1) / threads;
        avg_kernel<<<blocks, threads>>>();
    }
    {
        out_kernel<<<OUT_GRID, OUT_BLOCK, SMEM_NODES * sizeof(float)>>>(mask, src, dst, out, E);
    }
}

// round 6
// speedup vs baseline: 1.7231x; 1.7231x over previous
#include <cuda_runtime.h>
#include <cuda_fp16.h>
#include <stdint.h>

#define N_NODES 100000
#define GAMMA 0.5f
#define FIX_SCALE 8388608.0f        // 2^23
#define INV_FIX_SCALE (1.0f / 8388608.0f)
#define OUT_GRID 152                // one persistent block per SM
#define OUT_BLOCK 1024
#define SMEM_BYTES (N_NODES * 2)    // full avg table as fp16: 195.3KB < 227KB limit

// packed per-node accumulator: high 32 = count, low 32 = fixed-point sum (2^23 scale)
__device__ unsigned long long g_pack[N_NODES];
__device__ __half g_avg_h[N_NODES];

__global__ void zero_kernel() {
    int i = blockIdx.x * blockDim.x + threadIdx.x;
    if (i < N_NODES) g_pack[i] = 0ull;
}

__device__ __forceinline__ unsigned long long pack_edge(float m) {
    unsigned fix = __float2uint_rn(m * FIX_SCALE);
    return (1ull << 32) | (unsigned long long)fix;
}

// Scatter: one 64-bit REDG per edge carrying both count(+1) and fixed-point mask sum.
// Measured at the REDG spread-address floor (~31us).
__global__ void scatter_kernel(const float* __restrict__ mask,
                               const int* __restrict__ src,
                               int E) {
    int i4 = (blockIdx.x * blockDim.x + threadIdx.x) * 4;
    if (i4 + 3 < E) {
        float4 m = __ldcg(reinterpret_cast<const float4*>(mask + i4));
        int4 s = __ldcg(reinterpret_cast<const int4*>(src + i4));
        if ((unsigned)s.x < N_NODES) atomicAdd(&g_pack[s.x], pack_edge(m.x));
        if ((unsigned)s.y < N_NODES) atomicAdd(&g_pack[s.y], pack_edge(m.y));
        if ((unsigned)s.z < N_NODES) atomicAdd(&g_pack[s.z], pack_edge(m.z));
        if ((unsigned)s.w < N_NODES) atomicAdd(&g_pack[s.w], pack_edge(m.w));
    } else {
        for (int i = i4; i < E; i++) {
            int s = src[i];
            if ((unsigned)s < N_NODES) atomicAdd(&g_pack[s], pack_edge(mask[i]));
        }
    }
}

__global__ void avg_kernel() {
    int i = blockIdx.x * blockDim.x + threadIdx.x;
    if (i < N_NODES) {
        unsigned long long p = g_pack[i];
        float cnt = (float)(unsigned)(p >> 32);
        float sum = (float)(unsigned)(p & 0xffffffffull) * INV_FIX_SCALE;
        g_avg_h[i] = __float2half_rn(sum / fmaxf(cnt, 1.0f));
    }
}

// out[e] = 0.5*mask[e] + 0.25*(avg[src[e]] + avg[dst[e]])
// Full fp16 avg table resides in smem: every lookup is a single LDS, no global
// gathers at all. Kernel is pure-streaming bound.
__global__ void __launch_bounds__(OUT_BLOCK, 1)
out_kernel(const float* __restrict__ mask,
           const int* __restrict__ src,
           const int* __restrict__ dst,
           float* __restrict__ out,
           int E) {
    extern __shared__ __half s_avg[];

    // Stage table: 195.3KB via 128-bit loads/stores (12500 uint4 chunks).
    {
        const uint4* gsrc = reinterpret_cast<const uint4*>(g_avg_h);
        uint4* sdst = reinterpret_cast<uint4*>(s_avg);
        const int nchunk = (N_NODES * 2) / 16;  // 12500
        for (int i = threadIdx.x; i < nchunk; i += OUT_BLOCK)
            sdst[i] = gsrc[i];
    }
    __syncthreads();

    int nG = E >> 2;
    int stride = gridDim.x * OUT_BLOCK;
    for (int g = blockIdx.x * OUT_BLOCK + threadIdx.x; g < nG; g += stride) {
        int i4 = g * 4;
        float4 m = __ldcg(reinterpret_cast<const float4*>(mask + i4));
        int4 s = __ldcg(reinterpret_cast<const int4*>(src + i4));
        int4 d = __ldcg(reinterpret_cast<const int4*>(dst + i4));

        unsigned cap = N_NODES - 1;
        float vs0 = __half2float(s_avg[min((unsigned)s.x, cap)]);
        float vs1 = __half2float(s_avg[min((unsigned)s.y, cap)]);
        float vs2 = __half2float(s_avg[min((unsigned)s.z, cap)]);
        float vs3 = __half2float(s_avg[min((unsigned)s.w, cap)]);
        float vd0 = __half2float(s_avg[min((unsigned)d.x, cap)]);
        float vd1 = __half2float(s_avg[min((unsigned)d.y, cap)]);
        float vd2 = __half2float(s_avg[min((unsigned)d.z, cap)]);
        float vd3 = __half2float(s_avg[min((unsigned)d.w, cap)]);

        float4 o;
        o.x = (1.0f - GAMMA) * m.x + (GAMMA * 0.5f) * (vs0 + vd0);
        o.y = (1.0f - GAMMA) * m.y + (GAMMA * 0.5f) * (vs1 + vd1);
        o.z = (1.0f - GAMMA) * m.z + (GAMMA * 0.5f) * (vs2 + vd2);
        o.w = (1.0f - GAMMA) * m.w + (GAMMA * 0.5f) * (vs3 + vd3);
        __stcg(reinterpret_cast<float4*>(out + i4), o);
    }

    // tail (E % 4 leftovers)
    int tail = E & 3;
    if (blockIdx.x == 0 && (int)threadIdx.x < tail) {
        int i = (E & ~3) + threadIdx.x;
        unsigned cap = N_NODES - 1;
        float a = __half2float(s_avg[min((unsigned)src[i], cap)]) +
                  __half2float(s_avg[min((unsigned)dst[i], cap)]);
        out[i] = (1.0f - GAMMA) * mask[i] + (GAMMA * 0.5f) * a;
    }
}

extern "C" void kernel_launch(void* const* d_in, const int* in_sizes, int n_in,
                              void* d_out, int out_size) {
    const float* mask = (const float*)d_in[0];
    const int* edge_index = (const int*)d_in[1];  // int32 (JAX x64 disabled)
    float* out = (float*)d_out;

    int E = in_sizes[0];
    const int* src = edge_index;       // row 0
    const int* dst = edge_index + E;   // row 1

    cudaFuncSetAttribute(out_kernel, cudaFuncAttributeMaxDynamicSharedMemorySize,
                         SMEM_BYTES);

    {
        int threads = 256;
        int blocks = (N_NODES + threads - 1) / threads;
        zero_kernel<<<blocks, threads>>>();
    }
    {
        int threads = 256;
        int work = (E + 3) / 4;
        int blocks = (work + threads - 1) / threads;
        scatter_kernel<<<blocks, threads>>>(mask, src, E);
    }
    {
        int threads = 256;
        int blocks = (N_NODES + threads - 1) / threads;
        avg_kernel<<<blocks, threads>>>();
    }
    {
        out_kernel<<<OUT_GRID, OUT_BLOCK, SMEM_BYTES>>>(mask, src, dst, out, E);
    }
}